// round 1
// baseline (speedup 1.0000x reference)
#include <cuda_runtime.h>
#include <cstdint>

// ---------------------------------------------------------------------------
// LSTM Neural Hawkes Process NLL  (B=64, L=1024, H=64)
//
// Kernel 1: per-batch persistent CTLSTM scan (64 CTAs x 448 threads)
// Kernel 2: Monte-Carlo intensity integral + event log-intensity (warp per (b,l))
// Kernel 3: deterministic reduction -> scalar NLL
// ---------------------------------------------------------------------------

#define BATCH   64
#define MAXL    1024
#define LP1     1025
#define HID     64
#define SEVENH  448
#define NMC     30
#define T_END   100.0f
#define EPS_L   1e-10f
#define TOTAL   (BATCH * LP1)          // 65600
#define HALF_ORIG 984000u              // (NMC*BATCH*LP1)/2 for original threefry layout

// RNG reproduction of jax.random.uniform(jax.random.key(42), (30,64,1025,1)):
//   0 = partitionable threefry (counts = uint64 iota; bits = out0 ^ out1)  [JAX >= 0.5 default]
//   1 = original threefry (uint32 iota split in halves; pair (i, i+half))
//   2 = partitionable, take out1 (low word)
//   3 = partitionable, take out0 (high word)
#define RNG_MODE 0

// ------------------------- device scratch (no mallocs) ---------------------
__device__ float g_before[BATCH * LP1 * HID];
__device__ float g_cs    [BATCH * LP1 * HID];
__device__ float g_cb    [BATCH * LP1 * HID];
__device__ float g_os    [BATCH * LP1 * HID];
__device__ float g_dc    [BATCH * LP1 * HID];
__device__ float g_dt    [TOTAL];
__device__ float g_part  [TOTAL];

// ------------------------------ math helpers --------------------------------
__device__ __forceinline__ float softplusf(float x) {
    // jax.nn.softplus = logaddexp(x, 0) = max(x,0) + log1p(exp(-|x|))
    return fmaxf(x, 0.0f) + log1pf(expf(-fabsf(x)));
}
__device__ __forceinline__ float sigmoidf(float x) {
    return 1.0f / (1.0f + expf(-x));
}

// ------------------------------ Threefry-2x32-20 ----------------------------
__device__ __forceinline__ uint32_t rotl32(uint32_t x, int r) {
    return (x << r) | (x >> (32 - r));
}
__device__ __forceinline__ uint2 threefry2x32(uint32_t k0, uint32_t k1,
                                              uint32_t x0, uint32_t x1) {
    uint32_t ks2 = k0 ^ k1 ^ 0x1BD11BDAu;
    x0 += k0; x1 += k1;
#define TF_R(r) { x0 += x1; x1 = rotl32(x1, (r)); x1 ^= x0; }
    TF_R(13) TF_R(15) TF_R(26) TF_R(6)   x0 += k1;  x1 += ks2 + 1u;
    TF_R(17) TF_R(29) TF_R(16) TF_R(24)  x0 += ks2; x1 += k0  + 2u;
    TF_R(13) TF_R(15) TF_R(26) TF_R(6)   x0 += k0;  x1 += k1  + 3u;
    TF_R(17) TF_R(29) TF_R(16) TF_R(24)  x0 += k1;  x1 += ks2 + 4u;
    TF_R(13) TF_R(15) TF_R(26) TF_R(6)   x0 += ks2; x1 += k0  + 5u;
#undef TF_R
    return make_uint2(x0, x1);
}

// u in [0,1) for flat index into the (30, 64, 1025, 1) uniform draw, key (0,42)
__device__ __forceinline__ float tf_uniform(uint32_t flat) {
#if RNG_MODE == 0
    uint2 r = threefry2x32(0u, 42u, 0u, flat);
    uint32_t bits = r.x ^ r.y;
#elif RNG_MODE == 1
    uint32_t x0, x1; bool lo = flat < HALF_ORIG;
    if (lo) { x0 = flat; x1 = flat + HALF_ORIG; }
    else    { x0 = flat - HALF_ORIG; x1 = flat; }
    uint2 r = threefry2x32(0u, 42u, x0, x1);
    uint32_t bits = lo ? r.x : r.y;
#elif RNG_MODE == 2
    uint2 r = threefry2x32(0u, 42u, 0u, flat);
    uint32_t bits = r.y;
#else
    uint2 r = threefry2x32(0u, 42u, 0u, flat);
    uint32_t bits = r.x;
#endif
    return __uint_as_float((bits >> 9) | 0x3F800000u) - 1.0f;
}

// ------------------------------ Kernel 1: scan -------------------------------
// One CTA per batch, 448 threads (one per column of the 7H-wide recurrent GEMM).
// Thread j keeps W_rec[:, j] (65 floats) in registers; h lives in shared and is
// broadcast. Threads 0..63 own hidden channel j and carry (c, cbar) in regs.
__global__ void __launch_bounds__(SEVENH, 1)
scan_kernel(const float* __restrict__ seq,    // [B, L, 1]
            const float* __restrict__ Wrec,   // [65, 448]
            const float* __restrict__ brec,   // [448]
            const int*   __restrict__ lens)   // [B]
{
    __shared__ __align__(16) float s_h[HID];   // current hidden state
    __shared__ float s_v[SEVENH];              // nonlinearized gate outputs
    __shared__ float s_dt[LP1];

    const int b = blockIdx.x;
    const int j = threadIdx.x;
    const int len = lens[b];
    const float* sp = seq + b * MAXL;

    // dt[l]: event gaps, -1 padding, final interval at l == len
    for (int l = j; l <= MAXL; l += SEVENH) {
        float v;
        if (l < len)        v = (l == 0) ? sp[0] : sp[l] - sp[l - 1];
        else if (l == len)  v = T_END - sp[len - 1];
        else                v = -1.0f;
        s_dt[l] = v;
        g_dt[b * LP1 + l] = v;
    }

    // index-0 outputs are the zero initial state
    if (j < HID) {
        const int base = (b * LP1) * HID + j;
        g_before[base] = 0.0f; g_cs[base] = 0.0f; g_cb[base] = 0.0f;
        g_os[base] = 0.0f;     g_dc[base] = 0.0f;
        s_h[j] = 0.0f;
    }

    // column weights in registers
    float w[65];
#pragma unroll
    for (int k = 0; k < 65; k++) w[k] = Wrec[k * SEVENH + j];
    const float bj = brec[j];

    float c_t = 0.0f, cbar = 0.0f;     // per-channel carries (threads j < 64)
    const int gate = j >> 6;           // 0:i 1:f 2:z 3:o 4:ib 5:fb 6:d
    __syncthreads();

    for (int l = 0; l < len; l++) {
        // v_j = b_j + w0*x + sum_k w[k+1]*h[k]   (4 accumulators to break chain)
        float a0 = fmaf(w[0], s_dt[l], bj);
        float a1 = 0.0f, a2 = 0.0f, a3 = 0.0f;
        const float4* h4 = reinterpret_cast<const float4*>(s_h);
#pragma unroll
        for (int q = 0; q < 16; q++) {
            float4 hv = h4[q];
            a0 = fmaf(w[4 * q + 1], hv.x, a0);
            a1 = fmaf(w[4 * q + 2], hv.y, a1);
            a2 = fmaf(w[4 * q + 3], hv.z, a2);
            a3 = fmaf(w[4 * q + 4], hv.w, a3);
        }
        float acc = (a0 + a1) + (a2 + a3);

        // apply this column's nonlinearity in place (parallel across 448 threads)
        float nv;
        if (gate == 2)      nv = tanhf(acc);        // z
        else if (gate == 6) nv = softplusf(acc);    // decay
        else                nv = sigmoidf(acc);     // i, f, o, ib, fb
        s_v[j] = nv;
        __syncthreads();

        if (j < HID) {
            const float iG = s_v[j],        fG  = s_v[HID + j];
            const float zG = s_v[2*HID + j], oG = s_v[3*HID + j];
            const float ib = s_v[4*HID + j], fb = s_v[5*HID + j];
            const float dec = s_v[6*HID + j];
            const float c   = fG * c_t + iG * zG;
            const float cb  = fb * cbar + ib * zG;
            const float cd  = cb + (c - cb) * expf(-dec * s_dt[l + 1]);
            const float bef = oG * tanhf(cd);
            c_t = cd; cbar = cb;
            s_h[j] = bef;
            const int base = (b * LP1 + l + 1) * HID + j;
            g_before[base] = bef; g_cs[base] = c; g_cb[base] = cb;
            g_os[base] = oG;      g_dc[base] = dec;
        }
        __syncthreads();
    }
}

// --------------------- Kernel 2: MC integral + log-intensity -----------------
// Warp per (b, l). Lane owns channels (lane, lane+32). 30 MC samples with
// bit-exact JAX threefry uniforms; warp-reduce the W_f dot per sample.
__global__ void __launch_bounds__(256, 8)
mc_kernel(const float* __restrict__ Wf,    // [64]
          const float* __restrict__ bf,    // [1]
          const int*   __restrict__ lens)  // [B]
{
    const int wid  = blockIdx.x * 8 + (threadIdx.x >> 5);
    if (wid >= TOTAL) return;
    const int lane = threadIdx.x & 31;
    const int b = wid / LP1;
    const int l = wid - b * LP1;
    const int len = lens[b];

    float out = 0.0f;
    if (l <= len) {
        const float dtl = g_dt[wid];
        const int base = wid * HID;
        const int h0 = lane, h1 = lane + 32;
        const float c0 = g_cs[base + h0], c1 = g_cs[base + h1];
        const float k0 = g_cb[base + h0], k1 = g_cb[base + h1];
        const float o0 = g_os[base + h0], o1 = g_os[base + h1];
        const float d0 = g_dc[base + h0], d1 = g_dc[base + h1];
        const float wf0 = Wf[h0], wf1 = Wf[h1];
        const float bfv = bf[0];

        // lane s (< 30) owns sample s's uniform draw: flat = s*65600 + wid
        const float u = tf_uniform((uint32_t)lane * (uint32_t)TOTAL + (uint32_t)wid);

        float acc = 0.0f;
#pragma unroll 5
        for (int s = 0; s < NMC; s++) {
            const float us = __shfl_sync(0xFFFFFFFFu, u, s);
            const float rt = us * dtl;
            const float hv0 = o0 * tanhf(k0 + (c0 - k0) * expf(-rt * d0));
            const float hv1 = o1 * tanhf(k1 + (c1 - k1) * expf(-rt * d1));
            float p = hv0 * wf0 + hv1 * wf1;
#pragma unroll
            for (int off = 16; off; off >>= 1)
                p += __shfl_xor_sync(0xFFFFFFFFu, p, off);
            acc += softplusf(p + bfv) + EPS_L;
        }
        const float lamb_int = (acc * (1.0f / NMC)) * dtl;

        float ev = 0.0f;
        if (l < len) {
            const float b0 = g_before[base + h0], b1 = g_before[base + h1];
            float q = b0 * wf0 + b1 * wf1;
#pragma unroll
            for (int off = 16; off; off >>= 1)
                q += __shfl_xor_sync(0xFFFFFFFFu, q, off);
            ev = logf(softplusf(q + bfv) + EPS_L);
        }
        out = ev - lamb_int;
    }
    if (lane == 0) g_part[wid] = out;
}

// --------------------------- Kernel 3: reduction -----------------------------
// NLL = -(1/B) * sum_b sum_l part[b,l] = -(sum of all partials)/B.
// Fixed strided assignment + fixed-order tree -> deterministic across replays.
__global__ void __launch_bounds__(1024, 1)
reduce_kernel(float* __restrict__ out)
{
    __shared__ float sh[1024];
    const int t = threadIdx.x;
    float s = 0.0f;
    for (int i = t; i < TOTAL; i += 1024) s += g_part[i];
    sh[t] = s;
    __syncthreads();
#pragma unroll
    for (int ofs = 512; ofs; ofs >>= 1) {
        if (t < ofs) sh[t] += sh[t + ofs];
        __syncthreads();
    }
    if (t == 0) out[0] = -sh[0] * (1.0f / BATCH);
}

// ------------------------------- launcher ------------------------------------
extern "C" void kernel_launch(void* const* d_in, const int* in_sizes, int n_in,
                              void* d_out, int out_size)
{
    // Identify inputs by element count (robust to metadata ordering).
    // seq_pads=65536, W_rec=29120, b_rec=448, b_f=1; W_f and seq_lens are both
    // 64 elements — W_f precedes seq_lens in any plausible ordering.
    const float* seq  = nullptr;
    const float* Wrec = nullptr;
    const float* brec = nullptr;
    const float* Wf   = nullptr;
    const float* bf   = nullptr;
    const int*   lens = nullptr;
    for (int i = 0; i < n_in; i++) {
        const int s = in_sizes[i];
        if      (s == BATCH * MAXL)     seq  = (const float*)d_in[i];
        else if (s == 65 * SEVENH)      Wrec = (const float*)d_in[i];
        else if (s == SEVENH)           brec = (const float*)d_in[i];
        else if (s == 1)                bf   = (const float*)d_in[i];
        else if (s == HID) {
            if (!Wf) Wf = (const float*)d_in[i];
            else     lens = (const int*)d_in[i];
        }
    }

    scan_kernel<<<BATCH, SEVENH>>>(seq, Wrec, brec, lens);
    mc_kernel<<<(TOTAL + 7) / 8, 256>>>(Wf, bf, lens);
    reduce_kernel<<<1, 1024>>>((float*)d_out);
}

// round 2
// speedup vs baseline: 1.2273x; 1.2273x over previous
#include <cuda_runtime.h>
#include <cstdint>

// ---------------------------------------------------------------------------
// LSTM Neural Hawkes Process NLL  (B=64, L=1024, H=64)
// R2: fma.rn.f32x2 packed GEMM, MUFU-approx transcendentals, fused epilogue.
// ---------------------------------------------------------------------------

#define BATCH   64
#define MAXL    1024
#define LP1     1025
#define HID     64
#define SEVENH  448
#define NMC     30
#define T_END   100.0f
#define EPS_L   1e-10f
#define TOTAL   (BATCH * LP1)          // 65600
#define LOG2E   1.4426950408889634f
#define LN2     0.6931471805599453f

// ------------------------- device scratch (no mallocs) ---------------------
__device__ float4 g_state [TOTAL * HID];   // {c, cbar, o, dec}
__device__ float  g_before[TOTAL * HID];
__device__ float  g_dt    [TOTAL];
__device__ float  g_part  [TOTAL];

// ------------------------------ fast math -----------------------------------
__device__ __forceinline__ float ex2f(float x){ float y; asm("ex2.approx.f32 %0,%1;":"=f"(y):"f"(x)); return y; }
__device__ __forceinline__ float lg2f(float x){ float y; asm("lg2.approx.f32 %0,%1;":"=f"(y):"f"(x)); return y; }
__device__ __forceinline__ float rcpf(float x){ float y; asm("rcp.approx.f32 %0,%1;":"=f"(y):"f"(x)); return y; }
__device__ __forceinline__ float tanh_mufu(float x){ float y; asm("tanh.approx.f32 %0,%1;":"=f"(y):"f"(x)); return y; }
__device__ __forceinline__ float fsig(float x){ return rcpf(1.0f + ex2f(-x * LOG2E)); }
__device__ __forceinline__ float ftanh(float x){            // ~1e-6 accurate (safe in recurrence)
    float t = ex2f(fminf(fmaxf(x, -15.0f), 15.0f) * (2.0f * LOG2E));
    return (t - 1.0f) * rcpf(t + 1.0f);
}
__device__ __forceinline__ float fsoftplus(float x){
    return fmaxf(x, 0.0f) + LN2 * lg2f(1.0f + ex2f(-fabsf(x) * LOG2E));
}
__device__ __forceinline__ float flog(float x){ return LN2 * lg2f(x); }

// ------------------------------ packed f32x2 --------------------------------
__device__ __forceinline__ void fma2(unsigned long long& d, unsigned long long a, unsigned long long b){
    asm("fma.rn.f32x2 %0, %1, %2, %0;" : "+l"(d) : "l"(a), "l"(b));
}
__device__ __forceinline__ unsigned long long pack2(float lo, float hi){
    unsigned long long r; asm("mov.b64 %0, {%1,%2};" : "=l"(r) : "f"(lo), "f"(hi)); return r;
}
__device__ __forceinline__ float2 unpack2(unsigned long long v){
    float2 r; asm("mov.b64 {%0,%1}, %2;" : "=f"(r.x), "=f"(r.y) : "l"(v)); return r;
}

// ------------------------------ Threefry-2x32-20 ----------------------------
__device__ __forceinline__ uint32_t rotl32(uint32_t x, int r){ return (x << r) | (x >> (32 - r)); }
__device__ __forceinline__ float tf_uniform(uint32_t flat){
    // partitionable threefry, key (0,42): bits = out0 ^ out1
    uint32_t k0 = 0u, k1 = 42u, ks2 = k0 ^ k1 ^ 0x1BD11BDAu;
    uint32_t x0 = 0u + k0, x1 = flat + k1;
#define TF_R(r) { x0 += x1; x1 = rotl32(x1, (r)); x1 ^= x0; }
    TF_R(13) TF_R(15) TF_R(26) TF_R(6)   x0 += k1;  x1 += ks2 + 1u;
    TF_R(17) TF_R(29) TF_R(16) TF_R(24)  x0 += ks2; x1 += k0  + 2u;
    TF_R(13) TF_R(15) TF_R(26) TF_R(6)   x0 += k0;  x1 += k1  + 3u;
    TF_R(17) TF_R(29) TF_R(16) TF_R(24)  x0 += k1;  x1 += ks2 + 4u;
    TF_R(13) TF_R(15) TF_R(26) TF_R(6)   x0 += ks2; x1 += k0  + 5u;
#undef TF_R
    uint32_t bits = x0 ^ x1;
    return __uint_as_float((bits >> 9) | 0x3F800000u) - 1.0f;
}

// ------------------------------ Kernel 1: scan -------------------------------
// One CTA per batch, 448 threads (one per GEMM output column). Column weights
// packed as 32 f32x2 pairs in registers; h broadcast from shared as float4.
// Epilogue on warps 12/13 (threads 384..447): thread 384+ch is ALSO the
// gate-6 (decay) thread for channel ch, so dec stays in-register and
// exp(-dec*dt_next) is precomputed in phase 1.
__global__ void __launch_bounds__(SEVENH, 1)
scan_kernel(const float* __restrict__ seq,    // [B, L, 1]
            const float* __restrict__ Wrec,   // [65, 448]
            const float* __restrict__ brec,   // [448]
            const int*   __restrict__ lens)   // [B]
{
    __shared__ __align__(16) float s_h[HID];
    __shared__ float s_v[SEVENH];
    __shared__ float s_dt[LP1];

    const int b = blockIdx.x;
    const int j = threadIdx.x;
    const int len = lens[b];
    const float* sp = seq + b * MAXL;

    for (int l = j; l <= MAXL; l += SEVENH) {
        float v;
        if (l < len)        v = (l == 0) ? sp[0] : sp[l] - sp[l - 1];
        else if (l == len)  v = T_END - sp[len - 1];
        else                v = -1.0f;
        s_dt[l] = v;
        g_dt[b * LP1 + l] = v;
    }

    if (j >= 384) {                     // epilogue threads init state index 0
        const int ch = j - 384;
        s_h[ch] = 0.0f;
        g_state [(b * LP1) * HID + ch] = make_float4(0.f, 0.f, 0.f, 0.f);
        g_before[(b * LP1) * HID + ch] = 0.0f;
    }

    // column weights: row 0 (x) scalar + 32 packed pairs for h rows 1..64
    const float w0 = Wrec[j];
    const float bj = brec[j];
    unsigned long long w2[32];
#pragma unroll
    for (int k = 0; k < 32; k++)
        w2[k] = pack2(Wrec[(2*k + 1) * SEVENH + j], Wrec[(2*k + 2) * SEVENH + j]);

    const int gate = j >> 6;            // 0:i 1:f 2:z 3:o 4:ib 5:fb 6:d
    float c_t = 0.0f, cbar = 0.0f;      // carries (epilogue threads only)
    __syncthreads();

    for (int l = 0; l < len; l++) {
        const float dtc = s_dt[l];

        // ---- phase 1: v_j = b_j + w0*dt + sum_k w[k]*h[k]  (packed f32x2)
        unsigned long long a0 = 0ull, a1 = 0ull, a2 = 0ull, a3 = 0ull;
        const float4* h4 = reinterpret_cast<const float4*>(s_h);
#pragma unroll
        for (int q = 0; q < 8; q++) {
            float4 u = h4[2*q], v = h4[2*q + 1];
            fma2(a0, w2[4*q + 0], pack2(u.x, u.y));
            fma2(a1, w2[4*q + 1], pack2(u.z, u.w));
            fma2(a2, w2[4*q + 2], pack2(v.x, v.y));
            fma2(a3, w2[4*q + 3], pack2(v.z, v.w));
        }
        float2 r0 = unpack2(a0), r1 = unpack2(a1), r2 = unpack2(a2), r3 = unpack2(a3);
        float acc = ((r0.x + r0.y) + (r1.x + r1.y))
                  + ((r2.x + r2.y) + (r3.x + r3.y)) + fmaf(w0, dtc, bj);

        float nv, e = 0.0f;
        if (gate == 2)      nv = ftanh(acc);
        else if (gate == 6) {
            nv = fsoftplus(acc);                          // dec (kept in-register)
            e  = ex2f(-nv * s_dt[l + 1] * LOG2E);         // exp(-dec*dt_next)
        }
        else                nv = fsig(acc);
        s_v[j] = nv;
        __syncthreads();

        // ---- phase 2: epilogue on warps 12/13 (thread 384+ch owns channel ch)
        if (j >= 384) {
            const int ch = j - 384;
            const float iG = s_v[ch],        fG = s_v[ 64 + ch];
            const float zG = s_v[128 + ch],  oG = s_v[192 + ch];
            const float ib = s_v[256 + ch],  fb = s_v[320 + ch];
            const float dec = nv;                         // own gate-6 output
            const float c   = fmaf(fG, c_t,  iG * zG);
            const float cb  = fmaf(fb, cbar, ib * zG);
            const float cd  = fmaf(c - cb, e, cb);
            const float bef = oG * ftanh(cd);
            c_t = cd; cbar = cb;
            s_h[ch] = bef;
            const int base = (b * LP1 + l + 1) * HID + ch;
            g_state [base] = make_float4(c, cb, oG, dec);
            g_before[base] = bef;
        }
        __syncthreads();
    }
}

// --------------------- Kernel 2: MC integral + log-intensity -----------------
// Warp per (b,l). Lane owns channels (lane, lane+32). 30 bit-exact JAX
// threefry uniforms; all transcendentals via MUFU approx (tanh.approx here:
// non-recurrent, error averages out across 30x65600 terms).
__global__ void __launch_bounds__(256, 8)
mc_kernel(const float* __restrict__ Wf,    // [64]
          const float* __restrict__ bf,    // [1]
          const int*   __restrict__ lens)  // [B]
{
    const int wid  = blockIdx.x * 8 + (threadIdx.x >> 5);
    if (wid >= TOTAL) return;
    const int lane = threadIdx.x & 31;
    const int b = wid / LP1;
    const int l = wid - b * LP1;
    const int len = lens[b];

    float out = 0.0f;
    if (l <= len) {
        const float dtl = g_dt[wid];
        const int base = wid * HID;
        const float4 s0 = g_state[base + lane];
        const float4 s1 = g_state[base + lane + 32];
        const float wf0 = Wf[lane], wf1 = Wf[lane + 32];
        const float bfv = bf[0];
        const float m0 = -s0.w * dtl * LOG2E, m1 = -s1.w * dtl * LOG2E;
        const float A0 = s0.x - s0.y,          A1 = s1.x - s1.y;

        // lane s (< 30) owns sample s's uniform: flat = s*65600 + wid
        const float u = tf_uniform((uint32_t)lane * (uint32_t)TOTAL + (uint32_t)wid);

        float acc = 0.0f;
#pragma unroll 6
        for (int s = 0; s < NMC; s++) {
            const float us = __shfl_sync(0xFFFFFFFFu, u, s);
            const float h0 = s0.z * tanh_mufu(fmaf(A0, ex2f(us * m0), s0.y));
            const float h1 = s1.z * tanh_mufu(fmaf(A1, ex2f(us * m1), s1.y));
            float p = fmaf(h0, wf0, h1 * wf1);
#pragma unroll
            for (int off = 16; off; off >>= 1)
                p += __shfl_xor_sync(0xFFFFFFFFu, p, off);
            acc += fsoftplus(p + bfv);
        }
        const float lamb_int = (acc * (1.0f / NMC) + EPS_L) * dtl;

        float ev = 0.0f;
        if (l < len) {
            const float b0 = g_before[base + lane], b1 = g_before[base + lane + 32];
            float q = fmaf(b0, wf0, b1 * wf1);
#pragma unroll
            for (int off = 16; off; off >>= 1)
                q += __shfl_xor_sync(0xFFFFFFFFu, q, off);
            ev = flog(fsoftplus(q + bfv) + EPS_L);
        }
        out = ev - lamb_int;
    }
    if (lane == 0) g_part[wid] = out;
}

// --------------------------- Kernel 3: reduction -----------------------------
__global__ void __launch_bounds__(1024, 1)
reduce_kernel(float* __restrict__ out)
{
    __shared__ float sh[1024];
    const int t = threadIdx.x;
    float s = 0.0f;
    for (int i = t; i < TOTAL; i += 1024) s += g_part[i];
    sh[t] = s;
    __syncthreads();
#pragma unroll
    for (int ofs = 512; ofs; ofs >>= 1) {
        if (t < ofs) sh[t] += sh[t + ofs];
        __syncthreads();
    }
    if (t == 0) out[0] = -sh[0] * (1.0f / BATCH);
}

// ------------------------------- launcher ------------------------------------
extern "C" void kernel_launch(void* const* d_in, const int* in_sizes, int n_in,
                              void* d_out, int out_size)
{
    const float* seq  = nullptr;
    const float* Wrec = nullptr;
    const float* brec = nullptr;
    const float* Wf   = nullptr;
    const float* bf   = nullptr;
    const int*   lens = nullptr;
    for (int i = 0; i < n_in; i++) {
        const int s = in_sizes[i];
        if      (s == BATCH * MAXL)     seq  = (const float*)d_in[i];
        else if (s == 65 * SEVENH)      Wrec = (const float*)d_in[i];
        else if (s == SEVENH)           brec = (const float*)d_in[i];
        else if (s == 1)                bf   = (const float*)d_in[i];
        else if (s == HID) {
            if (!Wf) Wf = (const float*)d_in[i];
            else     lens = (const int*)d_in[i];
        }
    }

    scan_kernel<<<BATCH, SEVENH>>>(seq, Wrec, brec, lens);
    mc_kernel<<<(TOTAL + 7) / 8, 256>>>(Wf, bf, lens);
    reduce_kernel<<<1, 1024>>>((float*)d_out);
}

// round 3
// speedup vs baseline: 1.3538x; 1.1031x over previous
#include <cuda_runtime.h>
#include <cstdint>

// ---------------------------------------------------------------------------
// LSTM Neural Hawkes Process NLL  (B=64, L=1024, H=64)
// R3: ulonglong2 h-pairs (no pack MOVs), single-MUFU tanh nonlins,
//     arrive/sync asymmetric barriers, lane-per-sample MC layout.
// ---------------------------------------------------------------------------

#define BATCH   64
#define MAXL    1024
#define LP1     1025
#define HID     64
#define SEVENH  448
#define NMC     30
#define T_END   100.0f
#define EPS_L   1e-10f
#define TOTAL   (BATCH * LP1)          // 65600
#define LOG2E   1.4426950408889634f
#define LN2     0.6931471805599453f

// ------------------------- device scratch (no mallocs) ---------------------
__device__ float4 g_state [TOTAL * HID];   // {c, cbar, o, dec}
__device__ float  g_before[TOTAL * HID];
__device__ float  g_dt    [TOTAL];
__device__ float  g_part  [TOTAL];

// ------------------------------ fast math -----------------------------------
__device__ __forceinline__ float ex2f(float x){ float y; asm("ex2.approx.f32 %0,%1;":"=f"(y):"f"(x)); return y; }
__device__ __forceinline__ float lg2f(float x){ float y; asm("lg2.approx.f32 %0,%1;":"=f"(y):"f"(x)); return y; }
__device__ __forceinline__ float tanh_mufu(float x){ float y; asm("tanh.approx.f32 %0,%1;":"=f"(y):"f"(x)); return y; }
__device__ __forceinline__ float fsig(float x){ return fmaf(0.5f, tanh_mufu(0.5f * x), 0.5f); }
__device__ __forceinline__ float fsoftplus(float x){
    return fmaxf(x, 0.0f) + LN2 * lg2f(1.0f + ex2f(-fabsf(x) * LOG2E));
}
__device__ __forceinline__ float flog(float x){ return LN2 * lg2f(x); }

// ------------------------------ packed f32x2 --------------------------------
__device__ __forceinline__ void fma2(unsigned long long& d, unsigned long long a, unsigned long long b){
    asm("fma.rn.f32x2 %0, %1, %2, %0;" : "+l"(d) : "l"(a), "l"(b));
}
__device__ __forceinline__ void add2(unsigned long long& d, unsigned long long a){
    asm("add.rn.f32x2 %0, %1, %0;" : "+l"(d) : "l"(a));
}
__device__ __forceinline__ unsigned long long pack2(float lo, float hi){
    unsigned long long r; asm("mov.b64 %0, {%1,%2};" : "=l"(r) : "f"(lo), "f"(hi)); return r;
}
__device__ __forceinline__ float2 unpack2(unsigned long long v){
    float2 r; asm("mov.b64 {%0,%1}, %2;" : "=f"(r.x), "=f"(r.y) : "l"(v)); return r;
}

// ------------------------------ named barriers ------------------------------
#define BAR_SYNC(id, cnt)   asm volatile("bar.sync %0, %1;"   :: "r"(id), "r"(cnt) : "memory")
#define BAR_ARRIVE(id, cnt) asm volatile("bar.arrive %0, %1;" :: "r"(id), "r"(cnt) : "memory")

// ------------------------------ Threefry-2x32-20 ----------------------------
__device__ __forceinline__ uint32_t rotl32(uint32_t x, int r){ return (x << r) | (x >> (32 - r)); }
__device__ __forceinline__ float tf_uniform(uint32_t flat){
    // JAX partitionable threefry, key (0,42): bits = out0 ^ out1
    uint32_t k0 = 0u, k1 = 42u, ks2 = k0 ^ k1 ^ 0x1BD11BDAu;
    uint32_t x0 = 0u + k0, x1 = flat + k1;
#define TF_R(r) { x0 += x1; x1 = rotl32(x1, (r)); x1 ^= x0; }
    TF_R(13) TF_R(15) TF_R(26) TF_R(6)   x0 += k1;  x1 += ks2 + 1u;
    TF_R(17) TF_R(29) TF_R(16) TF_R(24)  x0 += ks2; x1 += k0  + 2u;
    TF_R(13) TF_R(15) TF_R(26) TF_R(6)   x0 += k0;  x1 += k1  + 3u;
    TF_R(17) TF_R(29) TF_R(16) TF_R(24)  x0 += k1;  x1 += ks2 + 4u;
    TF_R(13) TF_R(15) TF_R(26) TF_R(6)   x0 += ks2; x1 += k0  + 5u;
#undef TF_R
    uint32_t bits = x0 ^ x1;
    return __uint_as_float((bits >> 9) | 0x3F800000u) - 1.0f;
}

// ------------------------------ Kernel 1: scan -------------------------------
// One CTA per batch, 448 threads (one per GEMM column). h kept in shared as
// f32x2 pairs so phase-1 LDS.128 yields two ready fma2 operands (no MOVs).
// Epilogue on warps 12/13 only; warps 0-11 use bar.arrive (non-blocking).
__global__ void __launch_bounds__(SEVENH, 1)
scan_kernel(const float* __restrict__ seq,    // [B, L, 1]
            const float* __restrict__ Wrec,   // [65, 448]
            const float* __restrict__ brec,   // [448]
            const int*   __restrict__ lens)   // [B]
{
    __shared__ __align__(16) float s_h[HID];
    __shared__ float s_v[SEVENH];
    __shared__ float s_dt[LP1];

    const int b = blockIdx.x;
    const int j = threadIdx.x;
    const int len = lens[b];
    const float* sp = seq + b * MAXL;

    for (int l = j; l <= MAXL; l += SEVENH) {
        float v;
        if (l < len)        v = (l == 0) ? sp[0] : sp[l] - sp[l - 1];
        else if (l == len)  v = T_END - sp[len - 1];
        else                v = -1.0f;
        s_dt[l] = v;
        g_dt[b * LP1 + l] = v;
    }

    if (j >= 384) {                     // epilogue threads init state index 0
        const int ch = j - 384;
        s_h[ch] = 0.0f;
        g_state [(b * LP1) * HID + ch] = make_float4(0.f, 0.f, 0.f, 0.f);
        g_before[(b * LP1) * HID + ch] = 0.0f;
    }

    // column weights: row 0 (x) scalar + 32 packed pairs for h rows 1..64
    const float w0 = Wrec[j];
    const float bj = brec[j];
    unsigned long long w2[32];
#pragma unroll
    for (int k = 0; k < 32; k++)
        w2[k] = pack2(Wrec[(2*k + 1) * SEVENH + j], Wrec[(2*k + 2) * SEVENH + j]);

    const int gate = j >> 6;            // 0:i 1:f 2:z 3:o 4:ib 5:fb 6:d
    float c_t = 0.0f, cbar = 0.0f;      // carries (epilogue threads only)
    __syncthreads();

    float dt_cur = s_dt[0];
    for (int l = 0; l < len; l++) {
        const float dt_nxt = s_dt[l + 1];

        // ---- phase 1: v_j = b_j + w0*dt + sum_k w[k]*h[k]  (packed f32x2)
        unsigned long long a0 = 0ull, a1 = 0ull, a2 = 0ull, a3 = 0ull;
        const ulonglong2* h2 = reinterpret_cast<const ulonglong2*>(s_h);
#pragma unroll
        for (int q = 0; q < 4; q++) {
            ulonglong2 u = h2[2*q], v = h2[2*q + 1];
            fma2(a0, w2[4*q + 0], u.x);
            fma2(a1, w2[4*q + 1], u.y);
            fma2(a2, w2[4*q + 2], v.x);
            fma2(a3, w2[4*q + 3], v.y);
            ulonglong2 s = h2[2*q + 8], t = h2[2*q + 9];
            fma2(a0, w2[4*q + 16], s.x);
            fma2(a1, w2[4*q + 17], s.y);
            fma2(a2, w2[4*q + 18], t.x);
            fma2(a3, w2[4*q + 19], t.y);
        }
        add2(a0, a1); add2(a2, a3); add2(a0, a2);
        float2 rr = unpack2(a0);
        float acc = (rr.x + rr.y) + fmaf(w0, dt_cur, bj);

        float nv, e = 0.0f;
        if (gate == 2)      nv = tanh_mufu(acc);
        else if (gate == 6) {
            nv = fsoftplus(acc);                          // dec
            e  = ex2f(-nv * dt_nxt * LOG2E);              // exp(-dec*dt_next)
        }
        else                nv = fsig(acc);
        s_v[j] = nv;

        if (j < 384) {
            BAR_ARRIVE(1, SEVENH);     // release s_v to epilogue, don't wait
        } else {
            BAR_SYNC(1, SEVENH);       // wait for all gates
            const int ch = j - 384;
            const float iG = s_v[ch],        fG = s_v[ 64 + ch];
            const float zG = s_v[128 + ch],  oG = s_v[192 + ch];
            const float ib = s_v[256 + ch],  fb = s_v[320 + ch];
            const float dec = nv;                         // own gate-6 output
            const float c   = fmaf(fG, c_t,  iG * zG);
            const float cb  = fmaf(fb, cbar, ib * zG);
            const float cd  = fmaf(c - cb, e, cb);
            const float bef = oG * tanh_mufu(cd);
            c_t = cd; cbar = cb;
            s_h[ch] = bef;
            const int base = (b * LP1 + l + 1) * HID + ch;
            g_state [base] = make_float4(c, cb, oG, dec);
            g_before[base] = bef;
        }
        BAR_SYNC(2, SEVENH);           // h ready for everyone
        dt_cur = dt_nxt;
    }
}

// --------------------- Kernel 2: MC integral + log-intensity -----------------
// Warp per (b,l); lane = MC sample (30 active). Per-channel params pre-
// transformed into shared {m, A, cbar, o*wf}; inner loop is LDS-broadcast +
// 2 MUFU + 3 FMA per channel with zero shuffles.
__global__ void __launch_bounds__(256, 8)
mc_kernel(const float* __restrict__ Wf,    // [64]
          const float* __restrict__ bf,    // [1]
          const int*   __restrict__ lens)  // [B]
{
    __shared__ __align__(16) float4 s_st[8][HID];

    const int warp = threadIdx.x >> 5;
    const int wid  = blockIdx.x * 8 + warp;
    if (wid >= TOTAL) return;
    const int lane = threadIdx.x & 31;
    const int b = wid / LP1;
    const int l = wid - b * LP1;
    const int len = lens[b];

    float out = 0.0f;
    if (l <= len) {
        const float dtl = g_dt[wid];
        const float bfv = bf[0];
        const int base = wid * HID;
        const float wf0 = Wf[lane], wf1 = Wf[lane + 32];

        // stage transformed per-channel params + event-term partial dot
        const float4 s0 = g_state[base + lane];
        const float4 s1 = g_state[base + lane + 32];
        const float mscale = -dtl * LOG2E;
        s_st[warp][lane]      = make_float4(s0.w * mscale, s0.x - s0.y, s0.y, s0.z * wf0);
        s_st[warp][lane + 32] = make_float4(s1.w * mscale, s1.x - s1.y, s1.y, s1.z * wf1);

        float q = 0.0f;
        if (l < len)
            q = fmaf(g_before[base + lane], wf0, g_before[base + lane + 32] * wf1);
        __syncwarp();

        // lane s: full 64-channel intensity at random time u_s * dt
        float sp = 0.0f;
        if (lane < NMC) {
            const float u = tf_uniform((uint32_t)lane * (uint32_t)TOTAL + (uint32_t)wid);
            float acc0 = 0.0f, acc1 = 0.0f;
            const float4* st = s_st[warp];
#pragma unroll 8
            for (int ch = 0; ch < HID; ch += 2) {
                const float4 t0 = st[ch], t1 = st[ch + 1];
                acc0 = fmaf(t0.w, tanh_mufu(fmaf(t0.y, ex2f(u * t0.x), t0.z)), acc0);
                acc1 = fmaf(t1.w, tanh_mufu(fmaf(t1.y, ex2f(u * t1.x), t1.z)), acc1);
            }
            sp = fsoftplus(acc0 + acc1 + bfv);
        }
        // sum softplus over 30 samples + event-term dot, one reduction pass
#pragma unroll
        for (int off = 16; off; off >>= 1) {
            sp += __shfl_xor_sync(0xFFFFFFFFu, sp, off);
            q  += __shfl_xor_sync(0xFFFFFFFFu, q,  off);
        }
        const float lamb_int = (sp * (1.0f / NMC) + EPS_L) * dtl;
        float ev = 0.0f;
        if (l < len) ev = flog(fsoftplus(q + bfv) + EPS_L);
        out = ev - lamb_int;
    }
    if (lane == 0) g_part[wid] = out;
}

// --------------------------- Kernel 3: reduction -----------------------------
__global__ void __launch_bounds__(1024, 1)
reduce_kernel(float* __restrict__ out)
{
    __shared__ float sh[1024];
    const int t = threadIdx.x;
    float s = 0.0f;
    for (int i = t; i < TOTAL; i += 1024) s += g_part[i];
    sh[t] = s;
    __syncthreads();
#pragma unroll
    for (int ofs = 512; ofs; ofs >>= 1) {
        if (t < ofs) sh[t] += sh[t + ofs];
        __syncthreads();
    }
    if (t == 0) out[0] = -sh[0] * (1.0f / BATCH);
}

// ------------------------------- launcher ------------------------------------
extern "C" void kernel_launch(void* const* d_in, const int* in_sizes, int n_in,
                              void* d_out, int out_size)
{
    const float* seq  = nullptr;
    const float* Wrec = nullptr;
    const float* brec = nullptr;
    const float* Wf   = nullptr;
    const float* bf   = nullptr;
    const int*   lens = nullptr;
    for (int i = 0; i < n_in; i++) {
        const int s = in_sizes[i];
        if      (s == BATCH * MAXL)     seq  = (const float*)d_in[i];
        else if (s == 65 * SEVENH)      Wrec = (const float*)d_in[i];
        else if (s == SEVENH)           brec = (const float*)d_in[i];
        else if (s == 1)                bf   = (const float*)d_in[i];
        else if (s == HID) {
            if (!Wf) Wf = (const float*)d_in[i];
            else     lens = (const int*)d_in[i];
        }
    }

    scan_kernel<<<BATCH, SEVENH>>>(seq, Wrec, brec, lens);
    mc_kernel<<<(TOTAL + 7) / 8, 256>>>(Wf, bf, lens);
    reduce_kernel<<<1, 1024>>>((float*)d_out);
}